// round 4
// baseline (speedup 1.0000x reference)
#include <cuda_runtime.h>
#include <cstdint>

#define N_NODES 262144
#define D 256

// ---------------- scratch ----------------
__device__ float g_hbuf[(size_t)N_NODES * D];   // embedding output (layer0 input)
__device__ float g_aggbuf[(size_t)N_NODES * D]; // neighbor sums
__device__ float g_xbuf[(size_t)N_NODES * D];   // layer0 output (layer1 input)

// ---------------- helpers ----------------
__device__ __forceinline__ uint32_t smem_u32(const void* p) {
    uint32_t a;
    asm("{ .reg .u64 t; cvta.to.shared.u64 t, %1; cvt.u32.u64 %0, t; }" : "=r"(a) : "l"(p));
    return a;
}

__device__ __forceinline__ void mma_tf32(float* d, const float* a, const float* b) {
    asm volatile(
        "mma.sync.aligned.m16n8k8.row.col.f32.tf32.tf32.f32 "
        "{%0,%1,%2,%3},{%4,%5,%6,%7},{%8,%9},{%0,%1,%2,%3};"
        : "+f"(d[0]), "+f"(d[1]), "+f"(d[2]), "+f"(d[3])
        : "r"(__float_as_uint(a[0])), "r"(__float_as_uint(a[1])),
          "r"(__float_as_uint(a[2])), "r"(__float_as_uint(a[3])),
          "r"(__float_as_uint(b[0])), "r"(__float_as_uint(b[1])));
}

#define CP_ASYNC16(dst, src) \
    asm volatile("cp.async.cg.shared.global [%0], [%1], 16;" :: "r"(dst), "l"(src))

// ---------------- small kernels ----------------
__device__ __forceinline__ void block_ln_stats(float v, float* sh, float& mean, float& rstd)
{
    int lane = threadIdx.x & 31;
    int w    = threadIdx.x >> 5;
    float s = v, q = v * v;
#pragma unroll
    for (int o = 16; o; o >>= 1) {
        s += __shfl_xor_sync(0xffffffffu, s, o);
        q += __shfl_xor_sync(0xffffffffu, q, o);
    }
    if (lane == 0) { sh[w] = s; sh[8 + w] = q; }
    __syncthreads();
    if (threadIdx.x == 0) {
        float ts = 0.f, tq = 0.f;
#pragma unroll
        for (int i = 0; i < 8; i++) { ts += sh[i]; tq += sh[8 + i]; }
        float m   = ts * (1.0f / 256.0f);
        float var = tq * (1.0f / 256.0f) - m * m;
        sh[16] = m;
        sh[17] = rsqrtf(var + 1e-5f);
    }
    __syncthreads();
    mean = sh[16];
    rstd = sh[17];
}

__global__ void embed_ln_kernel(const int* __restrict__ node_emb, const int* __restrict__ pos,
                                const float* __restrict__ node_tab, const float* __restrict__ pos_tab,
                                const float* __restrict__ gw, const float* __restrict__ bw,
                                float* __restrict__ out)
{
    __shared__ float sh[18];
    int row = blockIdx.x;
    int c   = threadIdx.x;
    int ne  = __ldg(node_emb + row);
    int p   = __ldg(pos + row);
    float v = node_tab[(size_t)ne * D + c] * 16.0f + pos_tab[(size_t)p * D + c];
    float m, r;
    block_ln_stats(v, sh, m, r);
    out[(size_t)row * D + c] = (v - m) * r * gw[c] + bw[c];
}

// agg[dst] += h[src]; one warp/edge, vector reds
__global__ void scatter_kernel(const int* __restrict__ src, const int* __restrict__ dst,
                               const float* __restrict__ h, float* __restrict__ agg, int nE)
{
    int e = blockIdx.x * 8 + (threadIdx.x >> 5);
    if (e >= nE) return;
    int lane = threadIdx.x & 31;
    int s = __ldg(src + e);
    int d = __ldg(dst + e);
    const float4* hs = (const float4*)(h + (size_t)s * D);
    float4 v0 = hs[lane];
    float4 v1 = hs[lane + 32];
    float* ag = agg + (size_t)d * D;
    asm volatile("red.global.add.v4.f32 [%0], {%1,%2,%3,%4};"
                 :: "l"(ag + lane * 4), "f"(v0.x), "f"(v0.y), "f"(v0.z), "f"(v0.w) : "memory");
    asm volatile("red.global.add.v4.f32 [%0], {%1,%2,%3,%4};"
                 :: "l"(ag + 128 + lane * 4), "f"(v1.x), "f"(v1.y), "f"(v1.z), "f"(v1.w) : "memory");
}

// ---------------- fused tf32 GEMM + bias/relu/residual/LN ----------------
// out = LN(relu(agg@Wl^T + bl + h@Wr^T) + h) * g + b
// CTA: 128 rows x 256 cols, K=512 over 16 stages of 32.
// 8 warps (2 row-groups x 4 col-groups), warp tile 64x64 (m4 n8).
// Swizzled smem: float4-granule g' = q ^ (row&7)  -> conflict-free LDS & STS.

#define OFF_BIAS 0
#define OFF_G    1024
#define OFF_B    2048
#define OFF_SUM  3072
#define OFF_SQ   5120
#define OFF_A0   8192
#define OFF_A1   24576
#define OFF_B0   40960
#define OFF_B1   73728
#define SMEM_BYTES 106496

__global__ __launch_bounds__(256, 1)
void gemm_ln_kernel(const float* __restrict__ agg, const float* __restrict__ h,
                    const float* __restrict__ Wl, const float* __restrict__ Wr,
                    const float* __restrict__ bl, const float* __restrict__ gw,
                    const float* __restrict__ bw, float* __restrict__ out)
{
    extern __shared__ char smem[];
    const uint32_t sb = smem_u32(smem);
    const int tid  = threadIdx.x;
    const int w    = tid >> 5;
    const int lane = tid & 31;
    const int g    = lane >> 2;
    const int t    = lane & 3;
    const int wr   = w & 1;   // row group (64 rows)
    const int wc   = w >> 1;  // col group (64 cols)
    const int rowBase = blockIdx.x * 128;

    float* biasS = (float*)(smem + OFF_BIAS);
    float* gS    = (float*)(smem + OFF_G);
    float* bS    = (float*)(smem + OFF_B);
    float* sumP  = (float*)(smem + OFF_SUM);   // [128][4]
    float* sqP   = (float*)(smem + OFF_SQ);    // [128][4]

    biasS[tid] = bl[tid];
    gS[tid]    = gw[tid];
    bS[tid]    = bw[tid];

    float acc[4][8][4];
#pragma unroll
    for (int i = 0; i < 4; i++)
#pragma unroll
        for (int j = 0; j < 8; j++)
#pragma unroll
            for (int q = 0; q < 4; q++) acc[i][j][q] = 0.f;

    // ---- software pipeline: 16 stages of K=32 ----
    // stage s: A = (s<8 ? agg : h) rows [rowBase,+128), k = (s&7)*32
    //          B = (s<8 ? Wl : Wr) rows [0,256), k same
    auto issue_load = [&](int s) {
        const float* A_ = (s < 8) ? agg : h;
        const float* B_ = (s < 8) ? Wl : Wr;
        const int k0 = (s & 7) * 32;
        const uint32_t aB = sb + OFF_A0 + (s & 1) * 16384;
        const uint32_t bB = sb + OFF_B0 + (s & 1) * 32768;
#pragma unroll
        for (int it = 0; it < 4; it++) {            // 1024 float4s
            int idx = tid + it * 256;
            int r = idx >> 3, q = idx & 7;
            const float* src = A_ + (size_t)(rowBase + r) * D + k0 + q * 4;
            CP_ASYNC16(aB + r * 128 + ((q ^ (r & 7)) << 4), src);
        }
#pragma unroll
        for (int it = 0; it < 8; it++) {            // 2048 float4s
            int idx = tid + it * 256;
            int n = idx >> 3, q = idx & 7;
            const float* src = B_ + (size_t)n * D + k0 + q * 4;
            CP_ASYNC16(bB + n * 128 + ((q ^ (n & 7)) << 4), src);
        }
        asm volatile("cp.async.commit_group;");
    };

    issue_load(0);

    const int t4 = t * 4;
    const uint32_t aRow = (wr * 64 + g) * 128;   // byte offset of row (i=0)
    const uint32_t bCol = (wc * 64 + g) * 128;   // byte offset of col (j=0)

    for (int s = 0; s < 16; s++) {
        if (s < 15) {
            issue_load(s + 1);
            asm volatile("cp.async.wait_group 1;" ::: "memory");
        } else {
            asm volatile("cp.async.wait_group 0;" ::: "memory");
        }
        __syncthreads();

        const char* sA = smem + OFF_A0 + (s & 1) * 16384;
        const char* sB = smem + OFF_B0 + (s & 1) * 32768;

#pragma unroll
        for (int kk = 0; kk < 32; kk += 8) {
            const int q0 = kk >> 2;
            const uint32_t off0 = (((q0 ^ g) << 4) | t4);
            const uint32_t off1 = ((((q0 + 1) ^ g) << 4) | t4);
            float a[4][4], b[8][2];
#pragma unroll
            for (int i = 0; i < 4; i++) {
                const char* p = sA + aRow + i * 2048;
                a[i][0] = *(const float*)(p + off0);
                a[i][1] = *(const float*)(p + 1024 + off0);
                a[i][2] = *(const float*)(p + off1);
                a[i][3] = *(const float*)(p + 1024 + off1);
            }
#pragma unroll
            for (int j = 0; j < 8; j++) {
                const char* p = sB + bCol + j * 1024;
                b[j][0] = *(const float*)(p + off0);
                b[j][1] = *(const float*)(p + off1);
            }
#pragma unroll
            for (int i = 0; i < 4; i++)
#pragma unroll
                for (int j = 0; j < 8; j++)
                    mma_tf32(acc[i][j], a[i], b[j]);
        }
        __syncthreads();
    }

    // ---- epilogue: v = relu(acc + bias) + h ; LN over 256 cols ----
    float s0[4], q0s[4], s1[4], q1s[4];
#pragma unroll
    for (int i = 0; i < 4; i++) {
        s0[i] = 0.f; q0s[i] = 0.f; s1[i] = 0.f; q1s[i] = 0.f;
        const int row0 = rowBase + wr * 64 + i * 16 + g;
#pragma unroll
        for (int j = 0; j < 8; j++) {
            const int c = wc * 64 + j * 8 + t * 2;
            const float b0 = biasS[c], b1 = biasS[c + 1];
            float2 h0 = *(const float2*)(h + (size_t)row0 * D + c);
            float2 h1 = *(const float2*)(h + (size_t)(row0 + 8) * D + c);
            float v0 = fmaxf(acc[i][j][0] + b0, 0.f) + h0.x;
            float v1 = fmaxf(acc[i][j][1] + b1, 0.f) + h0.y;
            float v2 = fmaxf(acc[i][j][2] + b0, 0.f) + h1.x;
            float v3 = fmaxf(acc[i][j][3] + b1, 0.f) + h1.y;
            acc[i][j][0] = v0; acc[i][j][1] = v1; acc[i][j][2] = v2; acc[i][j][3] = v3;
            s0[i] += v0 + v1;  q0s[i] += v0 * v0 + v1 * v1;
            s1[i] += v2 + v3;  q1s[i] += v2 * v2 + v3 * v3;
        }
    }
    // reduce over the 4 t-lanes (lanes g*4 + t)
#pragma unroll
    for (int i = 0; i < 4; i++) {
#pragma unroll
        for (int o = 1; o <= 2; o <<= 1) {
            s0[i]  += __shfl_xor_sync(0xffffffffu, s0[i], o);
            q0s[i] += __shfl_xor_sync(0xffffffffu, q0s[i], o);
            s1[i]  += __shfl_xor_sync(0xffffffffu, s1[i], o);
            q1s[i] += __shfl_xor_sync(0xffffffffu, q1s[i], o);
        }
    }
    if (t == 0) {
#pragma unroll
        for (int i = 0; i < 4; i++) {
            const int r0 = wr * 64 + i * 16 + g;
            sumP[r0 * 4 + wc] = s0[i];       sqP[r0 * 4 + wc] = q0s[i];
            sumP[(r0 + 8) * 4 + wc] = s1[i]; sqP[(r0 + 8) * 4 + wc] = q1s[i];
        }
    }
    __syncthreads();

#pragma unroll
    for (int i = 0; i < 4; i++) {
        const int r0 = wr * 64 + i * 16 + g;
        float4 sp0 = *(const float4*)(sumP + r0 * 4);
        float4 qp0 = *(const float4*)(sqP + r0 * 4);
        float4 sp1 = *(const float4*)(sumP + (r0 + 8) * 4);
        float4 qp1 = *(const float4*)(sqP + (r0 + 8) * 4);
        float m0 = (sp0.x + sp0.y + sp0.z + sp0.w) * (1.0f / 256.0f);
        float m1 = (sp1.x + sp1.y + sp1.z + sp1.w) * (1.0f / 256.0f);
        float r0v = rsqrtf((qp0.x + qp0.y + qp0.z + qp0.w) * (1.0f / 256.0f) - m0 * m0 + 1e-5f);
        float r1v = rsqrtf((qp1.x + qp1.y + qp1.z + qp1.w) * (1.0f / 256.0f) - m1 * m1 + 1e-5f);
        const size_t gr0 = (size_t)(rowBase + r0) * D;
        const size_t gr1 = gr0 + 8 * D;
#pragma unroll
        for (int j = 0; j < 8; j++) {
            const int c = wc * 64 + j * 8 + t * 2;
            const float gg0 = gS[c], gg1 = gS[c + 1];
            const float bb0 = bS[c], bb1 = bS[c + 1];
            float2 o0, o1;
            o0.x = (acc[i][j][0] - m0) * r0v * gg0 + bb0;
            o0.y = (acc[i][j][1] - m0) * r0v * gg1 + bb1;
            o1.x = (acc[i][j][2] - m1) * r1v * gg0 + bb0;
            o1.y = (acc[i][j][3] - m1) * r1v * gg1 + bb1;
            *(float2*)(out + gr0 + c) = o0;
            *(float2*)(out + gr1 + c) = o1;
        }
    }
}

// ---------------- launch ----------------
extern "C" void kernel_launch(void* const* d_in, const int* in_sizes, int n_in,
                              void* d_out, int out_size)
{
    const int*   node_emb = (const int*)d_in[0];
    const int*   pos      = (const int*)d_in[1];
    const int*   edge     = (const int*)d_in[2];
    const float* node_tab = (const float*)d_in[3];
    const float* pos_tab  = (const float*)d_in[4];
    const float* g_emb    = (const float*)d_in[5];
    const float* b_emb    = (const float*)d_in[6];
    const float* Wl0 = (const float*)d_in[7];
    const float* bl0 = (const float*)d_in[8];
    const float* Wr0 = (const float*)d_in[9];
    const float* g0  = (const float*)d_in[10];
    const float* b0  = (const float*)d_in[11];
    const float* Wl1 = (const float*)d_in[12];
    const float* bl1 = (const float*)d_in[13];
    const float* Wr1 = (const float*)d_in[14];
    const float* g1  = (const float*)d_in[15];
    const float* b1  = (const float*)d_in[16];
    float* out = (float*)d_out;

    const int nE = in_sizes[2] / 2;
    const int* srcp = edge;
    const int* dstp = edge + nE;

    float *h, *agg, *x;
    cudaGetSymbolAddress((void**)&h,   g_hbuf);
    cudaGetSymbolAddress((void**)&agg, g_aggbuf);
    cudaGetSymbolAddress((void**)&x,   g_xbuf);

    cudaFuncSetAttribute(gemm_ln_kernel, cudaFuncAttributeMaxDynamicSharedMemorySize, SMEM_BYTES);

    const int scatterBlocks = (nE + 7) / 8;
    const int gemmBlocks    = N_NODES / 128;  // 2048
    const size_t aggBytes   = (size_t)N_NODES * D * sizeof(float);

    embed_ln_kernel<<<N_NODES, 256>>>(node_emb, pos, node_tab, pos_tab, g_emb, b_emb, h);

    // Layer 0: h -> x
    cudaMemsetAsync(agg, 0, aggBytes);
    scatter_kernel<<<scatterBlocks, 256>>>(srcp, dstp, h, agg, nE);
    gemm_ln_kernel<<<gemmBlocks, 256, SMEM_BYTES>>>(agg, h, Wl0, Wr0, bl0, g0, b0, x);

    // Layer 1: x -> out
    cudaMemsetAsync(agg, 0, aggBytes);
    scatter_kernel<<<scatterBlocks, 256>>>(srcp, dstp, x, agg, nE);
    gemm_ln_kernel<<<gemmBlocks, 256, SMEM_BYTES>>>(agg, x, Wl1, Wr1, bl1, g1, b1, out);
}

// round 5
// speedup vs baseline: 1.0027x; 1.0027x over previous
#include <cuda_runtime.h>
#include <cstdint>

#define N_NODES 262144
#define D 256

// ---------------- scratch ----------------
__device__ float g_hbuf[(size_t)N_NODES * D];   // embedding output (layer0 input)
__device__ float g_aggbuf[(size_t)N_NODES * D]; // neighbor sums
__device__ float g_xbuf[(size_t)N_NODES * D];   // layer0 output (layer1 input)

// ---------------- helpers ----------------
__device__ __forceinline__ uint32_t smem_u32(const void* p) {
    uint32_t a;
    asm("{ .reg .u64 t; cvta.to.shared.u64 t, %1; cvt.u32.u64 %0, t; }" : "=r"(a) : "l"(p));
    return a;
}

__device__ __forceinline__ void mma_tf32(float* d, const float* a, const float* b) {
    asm volatile(
        "mma.sync.aligned.m16n8k8.row.col.f32.tf32.tf32.f32 "
        "{%0,%1,%2,%3},{%4,%5,%6,%7},{%8,%9},{%0,%1,%2,%3};"
        : "+f"(d[0]), "+f"(d[1]), "+f"(d[2]), "+f"(d[3])
        : "r"(__float_as_uint(a[0])), "r"(__float_as_uint(a[1])),
          "r"(__float_as_uint(a[2])), "r"(__float_as_uint(a[3])),
          "r"(__float_as_uint(b[0])), "r"(__float_as_uint(b[1])));
}

#define CP_ASYNC16(dst, src) \
    asm volatile("cp.async.cg.shared.global [%0], [%1], 16;" :: "r"(dst), "l"(src))

// ---------------- small kernels ----------------
__device__ __forceinline__ void block_ln_stats(float v, float* sh, float& mean, float& rstd)
{
    int lane = threadIdx.x & 31;
    int w    = threadIdx.x >> 5;
    float s = v, q = v * v;
#pragma unroll
    for (int o = 16; o; o >>= 1) {
        s += __shfl_xor_sync(0xffffffffu, s, o);
        q += __shfl_xor_sync(0xffffffffu, q, o);
    }
    if (lane == 0) { sh[w] = s; sh[8 + w] = q; }
    __syncthreads();
    if (threadIdx.x == 0) {
        float ts = 0.f, tq = 0.f;
#pragma unroll
        for (int i = 0; i < 8; i++) { ts += sh[i]; tq += sh[8 + i]; }
        float m   = ts * (1.0f / 256.0f);
        float var = tq * (1.0f / 256.0f) - m * m;
        sh[16] = m;
        sh[17] = rsqrtf(var + 1e-5f);
    }
    __syncthreads();
    mean = sh[16];
    rstd = sh[17];
}

__global__ void embed_ln_kernel(const int* __restrict__ node_emb, const int* __restrict__ pos,
                                const float* __restrict__ node_tab, const float* __restrict__ pos_tab,
                                const float* __restrict__ gw, const float* __restrict__ bw,
                                float* __restrict__ out)
{
    __shared__ float sh[18];
    int row = blockIdx.x;
    int c   = threadIdx.x;
    int ne  = __ldg(node_emb + row);
    int p   = __ldg(pos + row);
    float v = node_tab[(size_t)ne * D + c] * 16.0f + pos_tab[(size_t)p * D + c];
    float m, r;
    block_ln_stats(v, sh, m, r);
    out[(size_t)row * D + c] = (v - m) * r * gw[c] + bw[c];
}

// agg[dst] += h[src]; one warp/edge, vector reds
__global__ void scatter_kernel(const int* __restrict__ src, const int* __restrict__ dst,
                               const float* __restrict__ h, float* __restrict__ agg, int nE)
{
    int e = blockIdx.x * 8 + (threadIdx.x >> 5);
    if (e >= nE) return;
    int lane = threadIdx.x & 31;
    int s = __ldg(src + e);
    int d = __ldg(dst + e);
    const float4* hs = (const float4*)(h + (size_t)s * D);
    float4 v0 = hs[lane];
    float4 v1 = hs[lane + 32];
    float* ag = agg + (size_t)d * D;
    asm volatile("red.global.add.v4.f32 [%0], {%1,%2,%3,%4};"
                 :: "l"(ag + lane * 4), "f"(v0.x), "f"(v0.y), "f"(v0.z), "f"(v0.w) : "memory");
    asm volatile("red.global.add.v4.f32 [%0], {%1,%2,%3,%4};"
                 :: "l"(ag + 128 + lane * 4), "f"(v1.x), "f"(v1.y), "f"(v1.z), "f"(v1.w) : "memory");
}

// ---------------- fused tf32 GEMM + bias/relu/residual/LN ----------------
// out = LN(relu(agg@Wl^T + bl + h@Wr^T) + h) * g + b
// CTA: 128 rows x 256 cols, K=512 over 16 stages of 32.
// 8 warps (2 row-groups x 4 col-groups), warp tile 64x64 (m4 n8).
// Swizzled smem: float4-granule g' = q ^ (row&7)  -> conflict-free LDS & STS.

#define OFF_BIAS 0
#define OFF_G    1024
#define OFF_B    2048
#define OFF_SUM  3072
#define OFF_SQ   5120
#define OFF_A0   8192
#define OFF_A1   24576
#define OFF_B0   40960
#define OFF_B1   73728
#define SMEM_BYTES 106496

__global__ __launch_bounds__(256, 1)
void gemm_ln_kernel(const float* __restrict__ agg, const float* __restrict__ h,
                    const float* __restrict__ Wl, const float* __restrict__ Wr,
                    const float* __restrict__ bl, const float* __restrict__ gw,
                    const float* __restrict__ bw, float* __restrict__ out)
{
    extern __shared__ char smem[];
    const uint32_t sb = smem_u32(smem);
    const int tid  = threadIdx.x;
    const int w    = tid >> 5;
    const int lane = tid & 31;
    const int g    = lane >> 2;
    const int t    = lane & 3;
    const int wr   = w & 1;   // row group (64 rows)
    const int wc   = w >> 1;  // col group (64 cols)
    const int rowBase = blockIdx.x * 128;

    float* biasS = (float*)(smem + OFF_BIAS);
    float* gS    = (float*)(smem + OFF_G);
    float* bS    = (float*)(smem + OFF_B);
    float* sumP  = (float*)(smem + OFF_SUM);   // [128][4]
    float* sqP   = (float*)(smem + OFF_SQ);    // [128][4]

    biasS[tid] = bl[tid];
    gS[tid]    = gw[tid];
    bS[tid]    = bw[tid];

    float acc[4][8][4];
#pragma unroll
    for (int i = 0; i < 4; i++)
#pragma unroll
        for (int j = 0; j < 8; j++)
#pragma unroll
            for (int q = 0; q < 4; q++) acc[i][j][q] = 0.f;

    // ---- software pipeline: 16 stages of K=32 ----
    // stage s: A = (s<8 ? agg : h) rows [rowBase,+128), k = (s&7)*32
    //          B = (s<8 ? Wl : Wr) rows [0,256), k same
    auto issue_load = [&](int s) {
        const float* A_ = (s < 8) ? agg : h;
        const float* B_ = (s < 8) ? Wl : Wr;
        const int k0 = (s & 7) * 32;
        const uint32_t aB = sb + OFF_A0 + (s & 1) * 16384;
        const uint32_t bB = sb + OFF_B0 + (s & 1) * 32768;
#pragma unroll
        for (int it = 0; it < 4; it++) {            // 1024 float4s
            int idx = tid + it * 256;
            int r = idx >> 3, q = idx & 7;
            const float* src = A_ + (size_t)(rowBase + r) * D + k0 + q * 4;
            CP_ASYNC16(aB + r * 128 + ((q ^ (r & 7)) << 4), src);
        }
#pragma unroll
        for (int it = 0; it < 8; it++) {            // 2048 float4s
            int idx = tid + it * 256;
            int n = idx >> 3, q = idx & 7;
            const float* src = B_ + (size_t)n * D + k0 + q * 4;
            CP_ASYNC16(bB + n * 128 + ((q ^ (n & 7)) << 4), src);
        }
        asm volatile("cp.async.commit_group;");
    };

    issue_load(0);

    const int t4 = t * 4;
    const uint32_t aRow = (wr * 64 + g) * 128;   // byte offset of row (i=0)
    const uint32_t bCol = (wc * 64 + g) * 128;   // byte offset of col (j=0)

    for (int s = 0; s < 16; s++) {
        if (s < 15) {
            issue_load(s + 1);
            asm volatile("cp.async.wait_group 1;" ::: "memory");
        } else {
            asm volatile("cp.async.wait_group 0;" ::: "memory");
        }
        __syncthreads();

        const char* sA = smem + OFF_A0 + (s & 1) * 16384;
        const char* sB = smem + OFF_B0 + (s & 1) * 32768;

#pragma unroll
        for (int kk = 0; kk < 32; kk += 8) {
            const int q0 = kk >> 2;
            const uint32_t off0 = (((q0 ^ g) << 4) | t4);
            const uint32_t off1 = ((((q0 + 1) ^ g) << 4) | t4);
            float a[4][4], b[8][2];
#pragma unroll
            for (int i = 0; i < 4; i++) {
                const char* p = sA + aRow + i * 2048;
                a[i][0] = *(const float*)(p + off0);
                a[i][1] = *(const float*)(p + 1024 + off0);
                a[i][2] = *(const float*)(p + off1);
                a[i][3] = *(const float*)(p + 1024 + off1);
            }
#pragma unroll
            for (int j = 0; j < 8; j++) {
                const char* p = sB + bCol + j * 1024;
                b[j][0] = *(const float*)(p + off0);
                b[j][1] = *(const float*)(p + off1);
            }
#pragma unroll
            for (int i = 0; i < 4; i++)
#pragma unroll
                for (int j = 0; j < 8; j++)
                    mma_tf32(acc[i][j], a[i], b[j]);
        }
        __syncthreads();
    }

    // ---- epilogue: v = relu(acc + bias) + h ; LN over 256 cols ----
    float s0[4], q0s[4], s1[4], q1s[4];
#pragma unroll
    for (int i = 0; i < 4; i++) {
        s0[i] = 0.f; q0s[i] = 0.f; s1[i] = 0.f; q1s[i] = 0.f;
        const int row0 = rowBase + wr * 64 + i * 16 + g;
#pragma unroll
        for (int j = 0; j < 8; j++) {
            const int c = wc * 64 + j * 8 + t * 2;
            const float b0 = biasS[c], b1 = biasS[c + 1];
            float2 h0 = *(const float2*)(h + (size_t)row0 * D + c);
            float2 h1 = *(const float2*)(h + (size_t)(row0 + 8) * D + c);
            float v0 = fmaxf(acc[i][j][0] + b0, 0.f) + h0.x;
            float v1 = fmaxf(acc[i][j][1] + b1, 0.f) + h0.y;
            float v2 = fmaxf(acc[i][j][2] + b0, 0.f) + h1.x;
            float v3 = fmaxf(acc[i][j][3] + b1, 0.f) + h1.y;
            acc[i][j][0] = v0; acc[i][j][1] = v1; acc[i][j][2] = v2; acc[i][j][3] = v3;
            s0[i] += v0 + v1;  q0s[i] += v0 * v0 + v1 * v1;
            s1[i] += v2 + v3;  q1s[i] += v2 * v2 + v3 * v3;
        }
    }
    // reduce over the 4 t-lanes (lanes g*4 + t)
#pragma unroll
    for (int i = 0; i < 4; i++) {
#pragma unroll
        for (int o = 1; o <= 2; o <<= 1) {
            s0[i]  += __shfl_xor_sync(0xffffffffu, s0[i], o);
            q0s[i] += __shfl_xor_sync(0xffffffffu, q0s[i], o);
            s1[i]  += __shfl_xor_sync(0xffffffffu, s1[i], o);
            q1s[i] += __shfl_xor_sync(0xffffffffu, q1s[i], o);
        }
    }
    if (t == 0) {
#pragma unroll
        for (int i = 0; i < 4; i++) {
            const int r0 = wr * 64 + i * 16 + g;
            sumP[r0 * 4 + wc] = s0[i];       sqP[r0 * 4 + wc] = q0s[i];
            sumP[(r0 + 8) * 4 + wc] = s1[i]; sqP[(r0 + 8) * 4 + wc] = q1s[i];
        }
    }
    __syncthreads();

#pragma unroll
    for (int i = 0; i < 4; i++) {
        const int r0 = wr * 64 + i * 16 + g;
        float4 sp0 = *(const float4*)(sumP + r0 * 4);
        float4 qp0 = *(const float4*)(sqP + r0 * 4);
        float4 sp1 = *(const float4*)(sumP + (r0 + 8) * 4);
        float4 qp1 = *(const float4*)(sqP + (r0 + 8) * 4);
        float m0 = (sp0.x + sp0.y + sp0.z + sp0.w) * (1.0f / 256.0f);
        float m1 = (sp1.x + sp1.y + sp1.z + sp1.w) * (1.0f / 256.0f);
        float r0v = rsqrtf((qp0.x + qp0.y + qp0.z + qp0.w) * (1.0f / 256.0f) - m0 * m0 + 1e-5f);
        float r1v = rsqrtf((qp1.x + qp1.y + qp1.z + qp1.w) * (1.0f / 256.0f) - m1 * m1 + 1e-5f);
        const size_t gr0 = (size_t)(rowBase + r0) * D;
        const size_t gr1 = gr0 + 8 * D;
#pragma unroll
        for (int j = 0; j < 8; j++) {
            const int c = wc * 64 + j * 8 + t * 2;
            const float gg0 = gS[c], gg1 = gS[c + 1];
            const float bb0 = bS[c], bb1 = bS[c + 1];
            float2 o0, o1;
            o0.x = (acc[i][j][0] - m0) * r0v * gg0 + bb0;
            o0.y = (acc[i][j][1] - m0) * r0v * gg1 + bb1;
            o1.x = (acc[i][j][2] - m1) * r1v * gg0 + bb0;
            o1.y = (acc[i][j][3] - m1) * r1v * gg1 + bb1;
            *(float2*)(out + gr0 + c) = o0;
            *(float2*)(out + gr1 + c) = o1;
        }
    }
}

// ---------------- launch ----------------
extern "C" void kernel_launch(void* const* d_in, const int* in_sizes, int n_in,
                              void* d_out, int out_size)
{
    const int*   node_emb = (const int*)d_in[0];
    const int*   pos      = (const int*)d_in[1];
    const int*   edge     = (const int*)d_in[2];
    const float* node_tab = (const float*)d_in[3];
    const float* pos_tab  = (const float*)d_in[4];
    const float* g_emb    = (const float*)d_in[5];
    const float* b_emb    = (const float*)d_in[6];
    const float* Wl0 = (const float*)d_in[7];
    const float* bl0 = (const float*)d_in[8];
    const float* Wr0 = (const float*)d_in[9];
    const float* g0  = (const float*)d_in[10];
    const float* b0  = (const float*)d_in[11];
    const float* Wl1 = (const float*)d_in[12];
    const float* bl1 = (const float*)d_in[13];
    const float* Wr1 = (const float*)d_in[14];
    const float* g1  = (const float*)d_in[15];
    const float* b1  = (const float*)d_in[16];
    float* out = (float*)d_out;

    const int nE = in_sizes[2] / 2;
    const int* srcp = edge;
    const int* dstp = edge + nE;

    float *h, *agg, *x;
    cudaGetSymbolAddress((void**)&h,   g_hbuf);
    cudaGetSymbolAddress((void**)&agg, g_aggbuf);
    cudaGetSymbolAddress((void**)&x,   g_xbuf);

    cudaFuncSetAttribute(gemm_ln_kernel, cudaFuncAttributeMaxDynamicSharedMemorySize, SMEM_BYTES);

    const int scatterBlocks = (nE + 7) / 8;
    const int gemmBlocks    = N_NODES / 128;  // 2048
    const size_t aggBytes   = (size_t)N_NODES * D * sizeof(float);

    embed_ln_kernel<<<N_NODES, 256>>>(node_emb, pos, node_tab, pos_tab, g_emb, b_emb, h);

    // Layer 0: h -> x
    cudaMemsetAsync(agg, 0, aggBytes);
    scatter_kernel<<<scatterBlocks, 256>>>(srcp, dstp, h, agg, nE);
    gemm_ln_kernel<<<gemmBlocks, 256, SMEM_BYTES>>>(agg, h, Wl0, Wr0, bl0, g0, b0, x);

    // Layer 1: x -> out
    cudaMemsetAsync(agg, 0, aggBytes);
    scatter_kernel<<<scatterBlocks, 256>>>(srcp, dstp, x, agg, nE);
    gemm_ln_kernel<<<gemmBlocks, 256, SMEM_BYTES>>>(agg, x, Wl1, Wr1, bl1, g1, b1, out);
}

// round 6
// speedup vs baseline: 1.3852x; 1.3815x over previous
#include <cuda_runtime.h>
#include <cuda_fp16.h>
#include <cstdint>

#define N_NODES 262144
#define D 256

// ---------------- scratch ----------------
__device__ float  g_hbuf[(size_t)N_NODES * D];   // h (fp32) for residual
__device__ float  g_xbuf[(size_t)N_NODES * D];   // x (fp32) for residual layer1
__device__ __half g_h16[(size_t)N_NODES * D];    // h (fp16) operand/scatter
__device__ __half g_x16[(size_t)N_NODES * D];    // x (fp16) operand/scatter
__device__ __half g_agg16[(size_t)N_NODES * D];  // neighbor sums (fp16)
__device__ __half g_w16[4 * 65536];              // Wl0,Wr0,Wl1,Wr1 in fp16

// ---------------- helpers ----------------
__device__ __forceinline__ uint32_t smem_u32(const void* p) {
    uint32_t a;
    asm("{ .reg .u64 t; cvta.to.shared.u64 t, %1; cvt.u32.u64 %0, t; }" : "=r"(a) : "l"(p));
    return a;
}

__device__ __forceinline__ void mma_f16(float* d, const uint32_t* a, uint32_t b0, uint32_t b1) {
    asm volatile(
        "mma.sync.aligned.m16n8k16.row.col.f32.f16.f16.f32 "
        "{%0,%1,%2,%3},{%4,%5,%6,%7},{%8,%9},{%0,%1,%2,%3};"
        : "+f"(d[0]), "+f"(d[1]), "+f"(d[2]), "+f"(d[3])
        : "r"(a[0]), "r"(a[1]), "r"(a[2]), "r"(a[3]), "r"(b0), "r"(b1));
}

#define LDSM4(r, a) \
    asm volatile("ldmatrix.sync.aligned.m8n8.x4.shared.b16 {%0,%1,%2,%3}, [%4];" \
        : "=r"((r)[0]), "=r"((r)[1]), "=r"((r)[2]), "=r"((r)[3]) : "r"(a))

#define CP_ASYNC16(dst, src) \
    asm volatile("cp.async.cg.shared.global [%0], [%1], 16;" :: "r"(dst), "l"(src))

// ---------------- small kernels ----------------
__device__ __forceinline__ void block_ln_stats(float v, float* sh, float& mean, float& rstd)
{
    int lane = threadIdx.x & 31;
    int w    = threadIdx.x >> 5;
    float s = v, q = v * v;
#pragma unroll
    for (int o = 16; o; o >>= 1) {
        s += __shfl_xor_sync(0xffffffffu, s, o);
        q += __shfl_xor_sync(0xffffffffu, q, o);
    }
    if (lane == 0) { sh[w] = s; sh[8 + w] = q; }
    __syncthreads();
    if (threadIdx.x == 0) {
        float ts = 0.f, tq = 0.f;
#pragma unroll
        for (int i = 0; i < 8; i++) { ts += sh[i]; tq += sh[8 + i]; }
        float m   = ts * (1.0f / 256.0f);
        float var = tq * (1.0f / 256.0f) - m * m;
        sh[16] = m;
        sh[17] = rsqrtf(var + 1e-5f);
    }
    __syncthreads();
    mean = sh[16];
    rstd = sh[17];
}

__global__ void embed_ln_kernel(const int* __restrict__ node_emb, const int* __restrict__ pos,
                                const float* __restrict__ node_tab, const float* __restrict__ pos_tab,
                                const float* __restrict__ gw, const float* __restrict__ bw,
                                float* __restrict__ out32, __half* __restrict__ out16)
{
    __shared__ float sh[18];
    int row = blockIdx.x;
    int c   = threadIdx.x;
    int ne  = __ldg(node_emb + row);
    int p   = __ldg(pos + row);
    float v = node_tab[(size_t)ne * D + c] * 16.0f + pos_tab[(size_t)p * D + c];
    float m, r;
    block_ln_stats(v, sh, m, r);
    float o = (v - m) * r * gw[c] + bw[c];
    out32[(size_t)row * D + c] = o;
    out16[(size_t)row * D + c] = __float2half_rn(o);
}

__global__ void wconv_kernel(const float* __restrict__ w, __half* __restrict__ o)
{
    int i = blockIdx.x * 256 + threadIdx.x;
    o[i] = __float2half_rn(w[i]);
}

// agg16[dst] += h16[src]; one warp per edge: 1 LDG.128 + 1 RED.128 per lane.
__global__ void scatter_kernel(const int* __restrict__ src, const int* __restrict__ dst,
                               const __half* __restrict__ h16, __half* __restrict__ agg16, int nE)
{
    int e = blockIdx.x * 8 + (threadIdx.x >> 5);
    if (e >= nE) return;
    int lane = threadIdx.x & 31;
    int s = __ldg(src + e);
    int d = __ldg(dst + e);
    const uint4* hs = (const uint4*)(h16 + (size_t)s * D);
    uint4 v = hs[lane];
    const __half* ag = agg16 + (size_t)d * D + lane * 8;
    asm volatile("red.global.add.noftz.v4.f16x2 [%0], {%1,%2,%3,%4};"
                 :: "l"(ag), "r"(v.x), "r"(v.y), "r"(v.z), "r"(v.w) : "memory");
}

// ---------------- fused fp16 GEMM + bias/relu/residual/LN ----------------
// out = LN(relu(agg@Wl^T + bl + h@Wr^T) + resid) * g + b
// CTA 128x256, K=512 over 8 stages of 64. 8 warps (2x4), warp tile 64x64.
// fp16 operands via ldmatrix.x4 from xor-swizzled smem (16B granule q ^= row&7).

#define OFF_BIAS 0
#define OFF_G    1024
#define OFF_B    2048
#define OFF_SUM  3072
#define OFF_SQ   5120
#define OFF_A0   8192
#define OFF_B0   40960
#define SMEM_BYTES 106496

__global__ __launch_bounds__(256, 1)
void gemm_ln_kernel(const __half* __restrict__ aggH, const __half* __restrict__ hH,
                    const float* __restrict__ resid32,
                    const __half* __restrict__ wl, const __half* __restrict__ wr,
                    const float* __restrict__ bl, const float* __restrict__ gw,
                    const float* __restrict__ bw,
                    float* __restrict__ out32, __half* __restrict__ out16)
{
    extern __shared__ char smem[];
    const uint32_t sb = smem_u32(smem);
    const int tid  = threadIdx.x;
    const int w    = tid >> 5;
    const int lane = tid & 31;
    const int g    = lane >> 2;
    const int t    = lane & 3;
    const int wr_  = w & 1;   // row group (64 rows)
    const int wc   = w >> 1;  // col group (64 cols)
    const int rowBase = blockIdx.x * 128;

    float* biasS = (float*)(smem + OFF_BIAS);
    float* gS    = (float*)(smem + OFF_G);
    float* bS    = (float*)(smem + OFF_B);
    float* sumP  = (float*)(smem + OFF_SUM);   // [128][4]
    float* sqP   = (float*)(smem + OFF_SQ);    // [128][4]

    biasS[tid] = bl[tid];
    gS[tid]    = gw[tid];
    bS[tid]    = bw[tid];

    float acc[4][8][4];
#pragma unroll
    for (int i = 0; i < 4; i++)
#pragma unroll
        for (int j = 0; j < 8; j++)
#pragma unroll
            for (int q = 0; q < 4; q++) acc[i][j][q] = 0.f;

    // stage s (0..7): A = (s<4 ? aggH : hH) rows [rowBase,+128), k0 = (s&3)*64
    //                 B = (s<4 ? wl : wr)  rows [0,256)
    auto issue_load = [&](int s) {
        const __half* A_ = (s < 4) ? aggH : hH;
        const __half* B_ = (s < 4) ? wl : wr;
        const int k0 = (s & 3) * 64;
        const uint32_t aB = sb + OFF_A0 + (s & 1) * 16384;
        const uint32_t bB = sb + OFF_B0 + (s & 1) * 32768;
#pragma unroll
        for (int it = 0; it < 4; it++) {            // A: 128 rows x 8 granules
            int idx = tid + it * 256;
            int r = idx >> 3, q = idx & 7;
            const __half* src = A_ + (size_t)(rowBase + r) * D + k0 + q * 8;
            CP_ASYNC16(aB + r * 128 + ((q ^ (r & 7)) << 4), src);
        }
#pragma unroll
        for (int it = 0; it < 8; it++) {            // B: 256 rows x 8 granules
            int idx = tid + it * 256;
            int n = idx >> 3, q = idx & 7;
            const __half* src = B_ + (size_t)n * D + k0 + q * 8;
            CP_ASYNC16(bB + n * 128 + ((q ^ (n & 7)) << 4), src);
        }
        asm volatile("cp.async.commit_group;");
    };

    issue_load(0);

    const int lane7  = lane & 7;
    const int lane15 = lane & 15;
    const int gOffA  = lane >> 4;         // A: lanes 16-31 take k-granule +1
    const int gOffB  = (lane >> 3) & 1;   // B: lanes 8-15 / 24-31 take k-granule +1
    const uint32_t aRowOff = (uint32_t)(wr_ * 64 + lane15) * 128;
    const uint32_t bRowOff = (uint32_t)(wc * 64 + lane7 + ((lane >> 4) << 3)) * 128;

    for (int s = 0; s < 8; s++) {
        if (s < 7) {
            issue_load(s + 1);
            asm volatile("cp.async.wait_group 1;" ::: "memory");
        } else {
            asm volatile("cp.async.wait_group 0;" ::: "memory");
        }
        __syncthreads();

        const uint32_t sA = sb + OFF_A0 + (s & 1) * 16384;
        const uint32_t sB = sb + OFF_B0 + (s & 1) * 32768;
        const uint32_t aBase = sA + aRowOff;
        const uint32_t bBase = sB + bRowOff;

#pragma unroll
        for (int kk8 = 0; kk8 < 8; kk8 += 2) {      // k16-steps within k64 stage
            const uint32_t aSw = (uint32_t)(((kk8 + gOffA) ^ lane7) << 4);
            const uint32_t bSw = (uint32_t)(((kk8 + gOffB) ^ lane7) << 4);
            uint32_t a[4][4], b[4][4];
#pragma unroll
            for (int i = 0; i < 4; i++)
                LDSM4(a[i], aBase + i * 2048 + aSw);
#pragma unroll
            for (int nb = 0; nb < 4; nb++)
                LDSM4(b[nb], bBase + nb * 2048 + bSw);
#pragma unroll
            for (int i = 0; i < 4; i++)
#pragma unroll
                for (int j = 0; j < 8; j++)
                    mma_f16(acc[i][j], a[i], b[j >> 1][(j & 1) * 2], b[j >> 1][(j & 1) * 2 + 1]);
        }
        __syncthreads();
    }

    // ---- epilogue: v = relu(acc + bias) + resid ; LN over 256 cols ----
    float s0[4], q0s[4], s1[4], q1s[4];
#pragma unroll
    for (int i = 0; i < 4; i++) {
        s0[i] = 0.f; q0s[i] = 0.f; s1[i] = 0.f; q1s[i] = 0.f;
        const int row0 = rowBase + wr_ * 64 + i * 16 + g;
#pragma unroll
        for (int j = 0; j < 8; j++) {
            const int c = wc * 64 + j * 8 + t * 2;
            const float b0 = biasS[c], b1 = biasS[c + 1];
            float2 h0 = *(const float2*)(resid32 + (size_t)row0 * D + c);
            float2 h1 = *(const float2*)(resid32 + (size_t)(row0 + 8) * D + c);
            float v0 = fmaxf(acc[i][j][0] + b0, 0.f) + h0.x;
            float v1 = fmaxf(acc[i][j][1] + b1, 0.f) + h0.y;
            float v2 = fmaxf(acc[i][j][2] + b0, 0.f) + h1.x;
            float v3 = fmaxf(acc[i][j][3] + b1, 0.f) + h1.y;
            acc[i][j][0] = v0; acc[i][j][1] = v1; acc[i][j][2] = v2; acc[i][j][3] = v3;
            s0[i] += v0 + v1;  q0s[i] += v0 * v0 + v1 * v1;
            s1[i] += v2 + v3;  q1s[i] += v2 * v2 + v3 * v3;
        }
    }
#pragma unroll
    for (int i = 0; i < 4; i++) {
#pragma unroll
        for (int o = 1; o <= 2; o <<= 1) {
            s0[i]  += __shfl_xor_sync(0xffffffffu, s0[i], o);
            q0s[i] += __shfl_xor_sync(0xffffffffu, q0s[i], o);
            s1[i]  += __shfl_xor_sync(0xffffffffu, s1[i], o);
            q1s[i] += __shfl_xor_sync(0xffffffffu, q1s[i], o);
        }
    }
    if (t == 0) {
#pragma unroll
        for (int i = 0; i < 4; i++) {
            const int r0 = wr_ * 64 + i * 16 + g;
            sumP[r0 * 4 + wc] = s0[i];       sqP[r0 * 4 + wc] = q0s[i];
            sumP[(r0 + 8) * 4 + wc] = s1[i]; sqP[(r0 + 8) * 4 + wc] = q1s[i];
        }
    }
    __syncthreads();

#pragma unroll
    for (int i = 0; i < 4; i++) {
        const int r0 = wr_ * 64 + i * 16 + g;
        float4 sp0 = *(const float4*)(sumP + r0 * 4);
        float4 qp0 = *(const float4*)(sqP + r0 * 4);
        float4 sp1 = *(const float4*)(sumP + (r0 + 8) * 4);
        float4 qp1 = *(const float4*)(sqP + (r0 + 8) * 4);
        float m0 = (sp0.x + sp0.y + sp0.z + sp0.w) * (1.0f / 256.0f);
        float m1 = (sp1.x + sp1.y + sp1.z + sp1.w) * (1.0f / 256.0f);
        float r0v = rsqrtf((qp0.x + qp0.y + qp0.z + qp0.w) * (1.0f / 256.0f) - m0 * m0 + 1e-5f);
        float r1v = rsqrtf((qp1.x + qp1.y + qp1.z + qp1.w) * (1.0f / 256.0f) - m1 * m1 + 1e-5f);
        const size_t gr0 = (size_t)(rowBase + r0) * D;
        const size_t gr1 = gr0 + 8 * D;
#pragma unroll
        for (int j = 0; j < 8; j++) {
            const int c = wc * 64 + j * 8 + t * 2;
            const float gg0 = gS[c], gg1 = gS[c + 1];
            const float bb0 = bS[c], bb1 = bS[c + 1];
            float2 o0, o1;
            o0.x = (acc[i][j][0] - m0) * r0v * gg0 + bb0;
            o0.y = (acc[i][j][1] - m0) * r0v * gg1 + bb1;
            o1.x = (acc[i][j][2] - m1) * r1v * gg0 + bb0;
            o1.y = (acc[i][j][3] - m1) * r1v * gg1 + bb1;
            *(float2*)(out32 + gr0 + c) = o0;
            *(float2*)(out32 + gr1 + c) = o1;
            if (out16) {
                *(__half2*)(out16 + gr0 + c) = __floats2half2_rn(o0.x, o0.y);
                *(__half2*)(out16 + gr1 + c) = __floats2half2_rn(o1.x, o1.y);
            }
        }
    }
}

// ---------------- launch ----------------
extern "C" void kernel_launch(void* const* d_in, const int* in_sizes, int n_in,
                              void* d_out, int out_size)
{
    const int*   node_emb = (const int*)d_in[0];
    const int*   pos      = (const int*)d_in[1];
    const int*   edge     = (const int*)d_in[2];
    const float* node_tab = (const float*)d_in[3];
    const float* pos_tab  = (const float*)d_in[4];
    const float* g_emb    = (const float*)d_in[5];
    const float* b_emb    = (const float*)d_in[6];
    const float* Wl0 = (const float*)d_in[7];
    const float* bl0 = (const float*)d_in[8];
    const float* Wr0 = (const float*)d_in[9];
    const float* g0  = (const float*)d_in[10];
    const float* b0  = (const float*)d_in[11];
    const float* Wl1 = (const float*)d_in[12];
    const float* bl1 = (const float*)d_in[13];
    const float* Wr1 = (const float*)d_in[14];
    const float* g1  = (const float*)d_in[15];
    const float* b1  = (const float*)d_in[16];
    float* out = (float*)d_out;

    const int nE = in_sizes[2] / 2;
    const int* srcp = edge;
    const int* dstp = edge + nE;

    float *h32, *x32;
    __half *h16, *x16, *agg16, *w16;
    cudaGetSymbolAddress((void**)&h32,   g_hbuf);
    cudaGetSymbolAddress((void**)&x32,   g_xbuf);
    cudaGetSymbolAddress((void**)&h16,   g_h16);
    cudaGetSymbolAddress((void**)&x16,   g_x16);
    cudaGetSymbolAddress((void**)&agg16, g_agg16);
    cudaGetSymbolAddress((void**)&w16,   g_w16);

    __half* wl0 = w16;
    __half* wr0 = w16 + 65536;
    __half* wl1 = w16 + 131072;
    __half* wr1 = w16 + 196608;

    cudaFuncSetAttribute(gemm_ln_kernel, cudaFuncAttributeMaxDynamicSharedMemorySize, SMEM_BYTES);

    const int scatterBlocks = (nE + 7) / 8;
    const int gemmBlocks    = N_NODES / 128;  // 2048
    const size_t aggBytes   = (size_t)N_NODES * D * sizeof(__half);

    wconv_kernel<<<256, 256>>>(Wl0, wl0);
    wconv_kernel<<<256, 256>>>(Wr0, wr0);
    wconv_kernel<<<256, 256>>>(Wl1, wl1);
    wconv_kernel<<<256, 256>>>(Wr1, wr1);

    embed_ln_kernel<<<N_NODES, 256>>>(node_emb, pos, node_tab, pos_tab, g_emb, b_emb, h32, h16);

    // Layer 0: (h32,h16) -> (x32,x16)
    cudaMemsetAsync(agg16, 0, aggBytes);
    scatter_kernel<<<scatterBlocks, 256>>>(srcp, dstp, h16, agg16, nE);
    gemm_ln_kernel<<<gemmBlocks, 256, SMEM_BYTES>>>(agg16, h16, h32, wl0, wr0,
                                                    bl0, g0, b0, x32, x16);

    // Layer 1: (x32,x16) -> out (fp32 only)
    cudaMemsetAsync(agg16, 0, aggBytes);
    scatter_kernel<<<scatterBlocks, 256>>>(srcp, dstp, x16, agg16, nE);
    gemm_ln_kernel<<<gemmBlocks, 256, SMEM_BYTES>>>(agg16, x16, x32, wl1, wr1,
                                                    bl1, g1, b1, out, (__half*)nullptr);
}

// round 7
// speedup vs baseline: 1.3874x; 1.0015x over previous
#include <cuda_runtime.h>
#include <cuda_fp16.h>
#include <cstdint>

#define N_NODES 262144
#define D 256

// ---------------- scratch ----------------
__device__ float  g_hbuf[(size_t)N_NODES * D];   // h (fp32) for residual
__device__ float  g_xbuf[(size_t)N_NODES * D];   // x (fp32) for residual layer1
__device__ __half g_h16[(size_t)N_NODES * D];    // h (fp16) operand/scatter
__device__ __half g_x16[(size_t)N_NODES * D];    // x (fp16) operand/scatter
__device__ __half g_agg16[(size_t)N_NODES * D];  // neighbor sums (fp16)
__device__ __half g_w16[4 * 65536];              // Wl0,Wr0,Wl1,Wr1 in fp16

// ---------------- helpers ----------------
__device__ __forceinline__ uint32_t smem_u32(const void* p) {
    uint32_t a;
    asm("{ .reg .u64 t; cvta.to.shared.u64 t, %1; cvt.u32.u64 %0, t; }" : "=r"(a) : "l"(p));
    return a;
}

__device__ __forceinline__ void mma_f16(float* d, const uint32_t* a, uint32_t b0, uint32_t b1) {
    asm volatile(
        "mma.sync.aligned.m16n8k16.row.col.f32.f16.f16.f32 "
        "{%0,%1,%2,%3},{%4,%5,%6,%7},{%8,%9},{%0,%1,%2,%3};"
        : "+f"(d[0]), "+f"(d[1]), "+f"(d[2]), "+f"(d[3])
        : "r"(a[0]), "r"(a[1]), "r"(a[2]), "r"(a[3]), "r"(b0), "r"(b1));
}

#define LDSM4(r, a) \
    asm volatile("ldmatrix.sync.aligned.m8n8.x4.shared.b16 {%0,%1,%2,%3}, [%4];" \
        : "=r"((r)[0]), "=r"((r)[1]), "=r"((r)[2]), "=r"((r)[3]) : "r"(a))

#define CP_ASYNC16(dst, src) \
    asm volatile("cp.async.cg.shared.global [%0], [%1], 16;" :: "r"(dst), "l"(src))

// ---------------- small kernels ----------------
__device__ __forceinline__ void block_ln_stats(float v, float* sh, float& mean, float& rstd)
{
    int lane = threadIdx.x & 31;
    int w    = threadIdx.x >> 5;
    float s = v, q = v * v;
#pragma unroll
    for (int o = 16; o; o >>= 1) {
        s += __shfl_xor_sync(0xffffffffu, s, o);
        q += __shfl_xor_sync(0xffffffffu, q, o);
    }
    if (lane == 0) { sh[w] = s; sh[8 + w] = q; }
    __syncthreads();
    if (threadIdx.x == 0) {
        float ts = 0.f, tq = 0.f;
#pragma unroll
        for (int i = 0; i < 8; i++) { ts += sh[i]; tq += sh[8 + i]; }
        float m   = ts * (1.0f / 256.0f);
        float var = tq * (1.0f / 256.0f) - m * m;
        sh[16] = m;
        sh[17] = rsqrtf(var + 1e-5f);
    }
    __syncthreads();
    mean = sh[16];
    rstd = sh[17];
}

__global__ void embed_ln_kernel(const int* __restrict__ node_emb, const int* __restrict__ pos,
                                const float* __restrict__ node_tab, const float* __restrict__ pos_tab,
                                const float* __restrict__ gw, const float* __restrict__ bw,
                                float* __restrict__ out32, __half* __restrict__ out16)
{
    __shared__ float sh[18];
    int row = blockIdx.x;
    int c   = threadIdx.x;
    int ne  = __ldg(node_emb + row);
    int p   = __ldg(pos + row);
    float v = node_tab[(size_t)ne * D + c] * 16.0f + pos_tab[(size_t)p * D + c];
    float m, r;
    block_ln_stats(v, sh, m, r);
    float o = (v - m) * r * gw[c] + bw[c];
    out32[(size_t)row * D + c] = o;
    out16[(size_t)row * D + c] = __float2half_rn(o);
}

__global__ void wconv_kernel(const float* __restrict__ w, __half* __restrict__ o)
{
    int i = blockIdx.x * 256 + threadIdx.x;
    o[i] = __float2half_rn(w[i]);
}

// agg16[dst] += h16[src]; one warp per edge: 1 LDG.128 + 1 RED.128 per lane.
__global__ void scatter_kernel(const int* __restrict__ src, const int* __restrict__ dst,
                               const __half* __restrict__ h16, __half* __restrict__ agg16, int nE)
{
    int e = blockIdx.x * 8 + (threadIdx.x >> 5);
    if (e >= nE) return;
    int lane = threadIdx.x & 31;
    int s = __ldg(src + e);
    int d = __ldg(dst + e);
    const uint4* hs = (const uint4*)(h16 + (size_t)s * D);
    uint4 v = hs[lane];
    const __half* ag = agg16 + (size_t)d * D + lane * 8;
    asm volatile("red.global.add.noftz.v4.f16x2 [%0], {%1,%2,%3,%4};"
                 :: "l"(ag), "r"(v.x), "r"(v.y), "r"(v.z), "r"(v.w) : "memory");
}

// ---------------- fused fp16 GEMM + bias/relu/residual/LN ----------------
// out = LN(relu(agg@Wl^T + bl + h@Wr^T) + resid) * g + b
// CTA 128x256, K=512 over 8 stages of 64. 16 warps (4 row x 4 col), warp tile 32x64.
// 3-stage cp.async pipeline; xor-swizzled smem (16B granule q ^= row&7) + ldmatrix.x4.

#define OFF_BIAS 0
#define OFF_G    1024
#define OFF_B    2048
#define OFF_SUM  3072
#define OFF_SQ   5120
#define OFF_A0   8192               // 3 x 16384
#define OFF_B0   57344              // 3 x 32768
#define SMEM_BYTES 155648

__global__ __launch_bounds__(512, 1)
void gemm_ln_kernel(const __half* __restrict__ aggH, const __half* __restrict__ hH,
                    const float* __restrict__ resid32,
                    const __half* __restrict__ wl, const __half* __restrict__ wr,
                    const float* __restrict__ bl, const float* __restrict__ gw,
                    const float* __restrict__ bw,
                    float* __restrict__ out32, __half* __restrict__ out16)
{
    extern __shared__ char smem[];
    const uint32_t sb = smem_u32(smem);
    const int tid  = threadIdx.x;
    const int w    = tid >> 5;
    const int lane = tid & 31;
    const int g    = lane >> 2;
    const int t    = lane & 3;
    const int wr_  = w & 3;   // row group (32 rows)
    const int wc   = w >> 2;  // col group (64 cols)
    const int rowBase = blockIdx.x * 128;

    float* biasS = (float*)(smem + OFF_BIAS);
    float* gS    = (float*)(smem + OFF_G);
    float* bS    = (float*)(smem + OFF_B);
    float* sumP  = (float*)(smem + OFF_SUM);   // [128][4]
    float* sqP   = (float*)(smem + OFF_SQ);    // [128][4]

    if (tid < 256) {
        biasS[tid] = bl[tid];
        gS[tid]    = gw[tid];
        bS[tid]    = bw[tid];
    }

    float acc[2][8][4];
#pragma unroll
    for (int i = 0; i < 2; i++)
#pragma unroll
        for (int j = 0; j < 8; j++)
#pragma unroll
            for (int q = 0; q < 4; q++) acc[i][j][q] = 0.f;

    // stage s (0..7): A = (s<4 ? aggH : hH) rows [rowBase,+128), k0 = (s&3)*64
    //                 B = (s<4 ? wl : wr)  rows [0,256)
    auto issue_load = [&](int s) {
        const __half* A_ = (s < 4) ? aggH : hH;
        const __half* B_ = (s < 4) ? wl : wr;
        const int k0 = (s & 3) * 64;
        const int buf = s % 3;
        const uint32_t aB = sb + OFF_A0 + buf * 16384;
        const uint32_t bB = sb + OFF_B0 + buf * 32768;
#pragma unroll
        for (int it = 0; it < 2; it++) {            // A: 1024 granules
            int idx = tid + it * 512;
            int r = idx >> 3, q = idx & 7;
            const __half* src = A_ + (size_t)(rowBase + r) * D + k0 + q * 8;
            CP_ASYNC16(aB + r * 128 + ((q ^ (r & 7)) << 4), src);
        }
#pragma unroll
        for (int it = 0; it < 4; it++) {            // B: 2048 granules
            int idx = tid + it * 512;
            int n = idx >> 3, q = idx & 7;
            const __half* src = B_ + (size_t)n * D + k0 + q * 8;
            CP_ASYNC16(bB + n * 128 + ((q ^ (n & 7)) << 4), src);
        }
        asm volatile("cp.async.commit_group;");
    };

    issue_load(0);
    issue_load(1);

    const int lane7  = lane & 7;
    const int lane15 = lane & 15;
    const int gOffA  = lane >> 4;         // A: lanes 16-31 take k-granule +1
    const int gOffB  = (lane >> 3) & 1;   // B: lanes 8-15 / 24-31 take k-granule +1
    const uint32_t aRowOff = (uint32_t)(wr_ * 32 + lane15) * 128;
    const uint32_t bRowOff = (uint32_t)(wc * 64 + lane7 + ((lane >> 4) << 3)) * 128;

    for (int s = 0; s < 8; s++) {
        if (s < 6) {
            issue_load(s + 2);
            asm volatile("cp.async.wait_group 2;" ::: "memory");
        } else if (s == 6) {
            asm volatile("cp.async.wait_group 1;" ::: "memory");
        } else {
            asm volatile("cp.async.wait_group 0;" ::: "memory");
        }
        __syncthreads();

        const int buf = s % 3;
        const uint32_t aBase = sb + OFF_A0 + buf * 16384 + aRowOff;
        const uint32_t bBase = sb + OFF_B0 + buf * 32768 + bRowOff;

#pragma unroll
        for (int kk8 = 0; kk8 < 8; kk8 += 2) {      // k16-steps within k64 stage
            const uint32_t aSw = (uint32_t)(((kk8 + gOffA) ^ lane7) << 4);
            const uint32_t bSw = (uint32_t)(((kk8 + gOffB) ^ lane7) << 4);
            uint32_t a[2][4], b[4][4];
#pragma unroll
            for (int i = 0; i < 2; i++)
                LDSM4(a[i], aBase + i * 2048 + aSw);
#pragma unroll
            for (int nb = 0; nb < 4; nb++)
                LDSM4(b[nb], bBase + nb * 2048 + bSw);
#pragma unroll
            for (int i = 0; i < 2; i++)
#pragma unroll
                for (int j = 0; j < 8; j++)
                    mma_f16(acc[i][j], a[i], b[j >> 1][(j & 1) * 2], b[j >> 1][(j & 1) * 2 + 1]);
        }
        __syncthreads();
    }

    // ---- epilogue: v = relu(acc + bias) + resid ; LN over 256 cols ----
    float s0[2], q0s[2], s1[2], q1s[2];
#pragma unroll
    for (int i = 0; i < 2; i++) {
        s0[i] = 0.f; q0s[i] = 0.f; s1[i] = 0.f; q1s[i] = 0.f;
        const int row0 = rowBase + wr_ * 32 + i * 16 + g;
#pragma unroll
        for (int j = 0; j < 8; j++) {
            const int c = wc * 64 + j * 8 + t * 2;
            const float b0 = biasS[c], b1 = biasS[c + 1];
            float2 h0 = *(const float2*)(resid32 + (size_t)row0 * D + c);
            float2 h1 = *(const float2*)(resid32 + (size_t)(row0 + 8) * D + c);
            float v0 = fmaxf(acc[i][j][0] + b0, 0.f) + h0.x;
            float v1 = fmaxf(acc[i][j][1] + b1, 0.f) + h0.y;
            float v2 = fmaxf(acc[i][j][2] + b0, 0.f) + h1.x;
            float v3 = fmaxf(acc[i][j][3] + b1, 0.f) + h1.y;
            acc[i][j][0] = v0; acc[i][j][1] = v1; acc[i][j][2] = v2; acc[i][j][3] = v3;
            s0[i] += v0 + v1;  q0s[i] += v0 * v0 + v1 * v1;
            s1[i] += v2 + v3;  q1s[i] += v2 * v2 + v3 * v3;
        }
    }
#pragma unroll
    for (int i = 0; i < 2; i++) {
#pragma unroll
        for (int o = 1; o <= 2; o <<= 1) {
            s0[i]  += __shfl_xor_sync(0xffffffffu, s0[i], o);
            q0s[i] += __shfl_xor_sync(0xffffffffu, q0s[i], o);
            s1[i]  += __shfl_xor_sync(0xffffffffu, s1[i], o);
            q1s[i] += __shfl_xor_sync(0xffffffffu, q1s[i], o);
        }
    }
    if (t == 0) {
#pragma unroll
        for (int i = 0; i < 2; i++) {
            const int r0 = wr_ * 32 + i * 16 + g;
            sumP[r0 * 4 + wc] = s0[i];       sqP[r0 * 4 + wc] = q0s[i];
            sumP[(r0 + 8) * 4 + wc] = s1[i]; sqP[(r0 + 8) * 4 + wc] = q1s[i];
        }
    }
    __syncthreads();

#pragma unroll
    for (int i = 0; i < 2; i++) {
        const int r0 = wr_ * 32 + i * 16 + g;
        float4 sp0 = *(const float4*)(sumP + r0 * 4);
        float4 qp0 = *(const float4*)(sqP + r0 * 4);
        float4 sp1 = *(const float4*)(sumP + (r0 + 8) * 4);
        float4 qp1 = *(const float4*)(sqP + (r0 + 8) * 4);
        float m0 = (sp0.x + sp0.y + sp0.z + sp0.w) * (1.0f / 256.0f);
        float m1 = (sp1.x + sp1.y + sp1.z + sp1.w) * (1.0f / 256.0f);
        float r0v = rsqrtf((qp0.x + qp0.y + qp0.z + qp0.w) * (1.0f / 256.0f) - m0 * m0 + 1e-5f);
        float r1v = rsqrtf((qp1.x + qp1.y + qp1.z + qp1.w) * (1.0f / 256.0f) - m1 * m1 + 1e-5f);
        const size_t gr0 = (size_t)(rowBase + r0) * D;
        const size_t gr1 = gr0 + 8 * D;
#pragma unroll
        for (int j = 0; j < 8; j++) {
            const int c = wc * 64 + j * 8 + t * 2;
            const float gg0 = gS[c], gg1 = gS[c + 1];
            const float bb0 = bS[c], bb1 = bS[c + 1];
            float2 o0, o1;
            o0.x = (acc[i][j][0] - m0) * r0v * gg0 + bb0;
            o0.y = (acc[i][j][1] - m0) * r0v * gg1 + bb1;
            o1.x = (acc[i][j][2] - m1) * r1v * gg0 + bb0;
            o1.y = (acc[i][j][3] - m1) * r1v * gg1 + bb1;
            *(float2*)(out32 + gr0 + c) = o0;
            *(float2*)(out32 + gr1 + c) = o1;
            if (out16) {
                *(__half2*)(out16 + gr0 + c) = __floats2half2_rn(o0.x, o0.y);
                *(__half2*)(out16 + gr1 + c) = __floats2half2_rn(o1.x, o1.y);
            }
        }
    }
}

// ---------------- launch ----------------
extern "C" void kernel_launch(void* const* d_in, const int* in_sizes, int n_in,
                              void* d_out, int out_size)
{
    const int*   node_emb = (const int*)d_in[0];
    const int*   pos      = (const int*)d_in[1];
    const int*   edge     = (const int*)d_in[2];
    const float* node_tab = (const float*)d_in[3];
    const float* pos_tab  = (const float*)d_in[4];
    const float* g_emb    = (const float*)d_in[5];
    const float* b_emb    = (const float*)d_in[6];
    const float* Wl0 = (const float*)d_in[7];
    const float* bl0 = (const float*)d_in[8];
    const float* Wr0 = (const float*)d_in[9];
    const float* g0  = (const float*)d_in[10];
    const float* b0  = (const float*)d_in[11];
    const float* Wl1 = (const float*)d_in[12];
    const float* bl1 = (const float*)d_in[13];
    const float* Wr1 = (const float*)d_in[14];
    const float* g1  = (const float*)d_in[15];
    const float* b1  = (const float*)d_in[16];
    float* out = (float*)d_out;

    const int nE = in_sizes[2] / 2;
    const int* srcp = edge;
    const int* dstp = edge + nE;

    float *h32, *x32;
    __half *h16, *x16, *agg16, *w16;
    cudaGetSymbolAddress((void**)&h32,   g_hbuf);
    cudaGetSymbolAddress((void**)&x32,   g_xbuf);
    cudaGetSymbolAddress((void**)&h16,   g_h16);
    cudaGetSymbolAddress((void**)&x16,   g_x16);
    cudaGetSymbolAddress((void**)&agg16, g_agg16);
    cudaGetSymbolAddress((void**)&w16,   g_w16);

    __half* wl0 = w16;
    __half* wr0 = w16 + 65536;
    __half* wl1 = w16 + 131072;
    __half* wr1 = w16 + 196608;

    cudaFuncSetAttribute(gemm_ln_kernel, cudaFuncAttributeMaxDynamicSharedMemorySize, SMEM_BYTES);

    const int scatterBlocks = (nE + 7) / 8;
    const int gemmBlocks    = N_NODES / 128;  // 2048
    const size_t aggBytes   = (size_t)N_NODES * D * sizeof(__half);

    wconv_kernel<<<256, 256>>>(Wl0, wl0);
    wconv_kernel<<<256, 256>>>(Wr0, wr0);
    wconv_kernel<<<256, 256>>>(Wl1, wl1);
    wconv_kernel<<<256, 256>>>(Wr1, wr1);

    embed_ln_kernel<<<N_NODES, 256>>>(node_emb, pos, node_tab, pos_tab, g_emb, b_emb, h32, h16);

    // Layer 0: (h32,h16) -> (x32,x16)
    cudaMemsetAsync(agg16, 0, aggBytes);
    scatter_kernel<<<scatterBlocks, 256>>>(srcp, dstp, h16, agg16, nE);
    gemm_ln_kernel<<<gemmBlocks, 512, SMEM_BYTES>>>(agg16, h16, h32, wl0, wr0,
                                                    bl0, g0, b0, x32, x16);

    // Layer 1: (x32,x16) -> out (fp32 only)
    cudaMemsetAsync(agg16, 0, aggBytes);
    scatter_kernel<<<scatterBlocks, 256>>>(srcp, dstp, x16, agg16, nE);
    gemm_ln_kernel<<<gemmBlocks, 512, SMEM_BYTES>>>(agg16, x16, x32, wl1, wr1,
                                                    bl1, g1, b1, out, (__half*)nullptr);
}